// round 1
// baseline (speedup 1.0000x reference)
#include <cuda_runtime.h>
#include <cstdint>
#include <cstddef>

#define THREADS 256
#define ITEMS   16
#define TILE_N  (THREADS * ITEMS)   /* 4096 */
#define MAX_TILES 1024              /* N = 4194304 -> 1024 tiles per curve */

// ---------------- lookback state (device globals; no allocation) ----------
__device__ int   g_flag[2][MAX_TILES];
__device__ float g_aggT[2][MAX_TILES];
__device__ float g_aggX[2][MAX_TILES];
__device__ float g_aggY[2][MAX_TILES];
__device__ float g_incT[2][MAX_TILES];
__device__ float g_incX[2][MAX_TILES];
__device__ float g_incY[2][MAX_TILES];

__global__ void reset_flags_kernel() {
    int i = blockIdx.x * blockDim.x + threadIdx.x;
    if (i < 2 * MAX_TILES) (&g_flag[0][0])[i] = 0;
}

// ---------------- block scan helpers ---------------------------------------
__device__ __forceinline__ float warp_iscan(float v, int lane) {
#pragma unroll
    for (int o = 1; o < 32; o <<= 1) {
        float n = __shfl_up_sync(0xffffffffu, v, o);
        if (lane >= o) v += n;
    }
    return v;
}

// exclusive block scan of v; total of all THREADS values returned in `total`
__device__ __forceinline__ float block_escan(float v, float* sw, float& total,
                                             int tid, int lane, int w) {
    float inc = warp_iscan(v, lane);
    if (lane == 31) sw[w] = inc;
    __syncthreads();
    if (tid < 32) {
        float x = (lane < THREADS / 32) ? sw[lane] : 0.0f;
        x = warp_iscan(x, lane);
        if (lane < THREADS / 32) sw[lane] = x;
    }
    __syncthreads();
    float off = (w > 0) ? sw[w - 1] : 0.0f;
    total = sw[THREADS / 32 - 1];
    return off + (inc - v);
}

// ---------------- main fused scan kernel ------------------------------------
// grid = (tiles, 2): blockIdx.y selects curve.
__global__ void __launch_bounds__(THREADS)
curve_scan_kernel(const float* __restrict__ vecA,
                  const float* __restrict__ vecB,
                  const float* __restrict__ the0A,
                  const float* __restrict__ the0B,
                  const float* __restrict__ startA,
                  const float* __restrict__ startB,
                  const float* __restrict__ dlp,
                  float* __restrict__ out, int n)
{
    const int curve = blockIdx.y;
    const int tile  = blockIdx.x;
    const float* __restrict__ vec = curve ? vecB : vecA;
    const float th0 = curve ? the0B[0] : the0A[0];
    const float stx = curve ? startB[0] : startA[0];
    const float sty = curve ? startB[1] : startA[1];
    const float dl  = dlp[0];
    float* outc = out + (size_t)curve * (size_t)2 * (size_t)(n + 1);

    __shared__ float  swS[THREADS / 32];            // scan scratch (reused safely: each
    __shared__ float  swX[THREADS / 32];            //  scan has its own buffer)
    __shared__ float  swY[THREADS / 32];
    __shared__ float  sPre[3];                      // broadcast of tile-exclusive prefix
    __shared__ float2 sExy[THREADS];                // per-thread exclusive disp within tile
    __shared__ float2 sStage[THREADS * (ITEMS + 1)];// skewed staging (bank-conflict free)

    const int tid  = threadIdx.x;
    const int lane = tid & 31;
    const int w    = tid >> 5;
    const int base = tile * TILE_N + tid * ITEMS;

    // --- load 16 angles, thread-local inclusive scan ---
    float t[ITEMS];
    {
        const float4* v4 = reinterpret_cast<const float4*>(vec + base);
#pragma unroll
        for (int k = 0; k < ITEMS / 4; k++) {
            float4 q = v4[k];
            t[4 * k + 0] = q.x; t[4 * k + 1] = q.y;
            t[4 * k + 2] = q.z; t[4 * k + 3] = q.w;
        }
    }
#pragma unroll
    for (int k = 1; k < ITEMS; k++) t[k] += t[k - 1];

    float totT;
    float te = block_escan(t[ITEMS - 1], swS, totT, tid, lane, w);

    // --- step vectors at tile-local base angle 0; local cumsum -> staging smem ---
    float cx = 0.f, cy = 0.f;
#pragma unroll
    for (int k = 0; k < ITEMS; k++) {
        float a = te + t[k];
        float sn, cs;
        sincosf(a, &sn, &cs);
        cx += dl * cs;
        cy += dl * sn;
        sStage[tid * (ITEMS + 1) + k] = make_float2(cx, cy);
    }
    float totX, totY;
    float ex = block_escan(cx, swX, totX, tid, lane, w);
    float ey = block_escan(cy, swY, totY, tid, lane, w);
    sExy[tid] = make_float2(ex, ey);

    // --- decoupled lookback (warp 0; CUB-style 32-wide window) ---
    if (w == 0) {
        if (lane == 0) {
            ((volatile float*)g_aggT[curve])[tile] = totT;
            ((volatile float*)g_aggX[curve])[tile] = totX;
            ((volatile float*)g_aggY[curve])[tile] = totY;
            __threadfence();
            atomicExch(&g_flag[curve][tile], 1);
        }
        float pT = 0.f, pX = 0.f, pY = 0.f;   // exclusive prefix (identity)
        if (tile > 0) {
            int windowEnd = tile;
            while (true) {
                int j = windowEnd - 1 - lane;
                int f;
                do {
                    f = (j >= 0) ? ((volatile int*)g_flag[curve])[j] : 2;
                } while (__any_sync(0xffffffffu, f == 0));
                __threadfence();

                float sT, sX, sY;
                if (j >= 0) {
                    if (f == 2) {
                        sT = ((volatile float*)g_incT[curve])[j];
                        sX = ((volatile float*)g_incX[curve])[j];
                        sY = ((volatile float*)g_incY[curve])[j];
                    } else {
                        sT = ((volatile float*)g_aggT[curve])[j];
                        sX = ((volatile float*)g_aggX[curve])[j];
                        sY = ((volatile float*)g_aggY[curve])[j];
                    }
                } else { sT = 0.f; sX = 0.f; sY = 0.f; }

                unsigned ball = __ballot_sync(0xffffffffu, f == 2);
                int firstInc = ball ? (__ffs(ball) - 1) : 32;
                if (lane > firstInc) { sT = 0.f; sX = 0.f; sY = 0.f; }

                // ordered tree reduction: lane l <- (lane l+off) ⊕ (lane l)
                // (higher lane = earlier tile; combine earlier-first)
#pragma unroll
                for (int off = 1; off < 32; off <<= 1) {
                    float oT = __shfl_down_sync(0xffffffffu, sT, off);
                    float oX = __shfl_down_sync(0xffffffffu, sX, off);
                    float oY = __shfl_down_sync(0xffffffffu, sY, off);
                    if (lane + off < 32) {
                        float sn, cs;
                        sincosf(oT, &sn, &cs);
                        float nX = oX + cs * sX - sn * sY;
                        float nY = oY + sn * sX + cs * sY;
                        sT = oT + sT; sX = nX; sY = nY;
                    }
                }
                if (lane == 0) {   // acc = W ⊕ acc
                    float sn, cs;
                    sincosf(sT, &sn, &cs);
                    float nX = sX + cs * pX - sn * pY;
                    float nY = sY + sn * pX + cs * pY;
                    pT = sT + pT; pX = nX; pY = nY;
                }
                if (firstInc < 32) break;
                windowEnd -= 32;
            }
        }
        if (lane == 0) {
            // publish inclusive = prefix ⊕ local
            float sn, cs;
            sincosf(pT, &sn, &cs);
            ((volatile float*)g_incT[curve])[tile] = pT + totT;
            ((volatile float*)g_incX[curve])[tile] = pX + cs * totX - sn * totY;
            ((volatile float*)g_incY[curve])[tile] = pY + sn * totX + cs * totY;
            __threadfence();
            atomicExch(&g_flag[curve][tile], 2);
            sPre[0] = pT; sPre[1] = pX; sPre[2] = pY;
        }
    }
    __syncthreads();

    // --- final affine transform + coalesced write-out ---
    const float pT = sPre[0], pX = sPre[1], pY = sPre[2];
    float s0, c0, sB, cB;
    sincosf(th0, &s0, &c0);
    sincosf(th0 + pT, &sB, &cB);
    const float bx = stx + c0 * pX - s0 * pY;
    const float by = sty + s0 * pX + c0 * pY;

    float2* dst = reinterpret_cast<float2*>(outc + 2 * (size_t)(tile * TILE_N) + 2);
#pragma unroll
    for (int k = 0; k < ITEMS; k++) {
        int p  = k * THREADS + tid;           // linear point index within tile
        int wt = p >> 4;                       // writer thread
        int kk = p & (ITEMS - 1);
        float2 l = sStage[wt * (ITEMS + 1) + kk];
        float2 e = sExy[wt];
        float ux = e.x + l.x;
        float uy = e.y + l.y;
        float px = bx + cB * ux - sB * uy;
        float py = by + sB * ux + cB * uy;
        dst[p] = make_float2(px, py);
    }

    if (tile == 0 && tid == 0) { outc[0] = stx; outc[1] = sty; }
}

// ---------------- launch ----------------------------------------------------
extern "C" void kernel_launch(void* const* d_in, const int* in_sizes, int n_in,
                              void* d_out, int out_size) {
    const float* vec   = (const float*)d_in[0];
    const float* vec2  = (const float*)d_in[1];
    const float* the0  = (const float*)d_in[2];
    const float* the02 = (const float*)d_in[3];
    const float* PS    = (const float*)d_in[4];
    const float* PE    = (const float*)d_in[5];
    const float* dl    = (const float*)d_in[6];
    float* out = (float*)d_out;

    int n = in_sizes[0];
    int tiles = n / TILE_N;

    reset_flags_kernel<<<(2 * MAX_TILES + THREADS - 1) / THREADS, THREADS>>>();
    dim3 grid(tiles, 2);
    curve_scan_kernel<<<grid, THREADS>>>(vec, vec2, the0, the02, PS, PE, dl, out, n);
}